// round 9
// baseline (speedup 1.0000x reference)
#include <cuda_runtime.h>
#include <cuda_bf16.h>
#include <cstdint>

#define NN 8192
#define CC 128

#if defined(__CUDA_ARCH_FEAT_SM103_ALL) || defined(__CUDA_ARCH_FEAT_SM100_ALL) || defined(__CUDA_ARCH_FEAT_SM101_ALL)
#define HAS_TCGEN05 1
#else
#define HAS_TCGEN05 0
#endif

// ---------------- scratch (__device__ globals: allocation-free rule) --------
__device__ float g_T1[NN * CC];
__device__ float g_P[2 * NN * CC];                 // split-K partials
__device__ __nv_bfloat16 g_Bt_hi[CC * NN];         // transposed B operand, hi
__device__ __nv_bfloat16 g_Bt_lo[CC * NN];         // transposed B operand, lo
__device__ unsigned g_cnt1, g_cnt2, g_cnt3;        // grid-barrier counters

// ---------------- PTX helpers (safe on all targets) -------------------------
__device__ __forceinline__ uint32_t smem_u32(const void* p) {
    uint32_t a;
    asm("{ .reg .u64 t; cvta.to.shared.u64 t, %1; cvt.u32.u64 %0, t; }" : "=r"(a) : "l"(p));
    return a;
}

#define MBARRIER_INIT(addr, cnt) \
    asm volatile("mbarrier.init.shared.b64 [%0], %1;" :: "r"((uint32_t)(addr)), "r"((uint32_t)(cnt)) : "memory")

#define MBARRIER_ARRIVE(addr) \
    asm volatile("mbarrier.arrive.release.cta.shared::cta.b64 _, [%0];" :: "r"((uint32_t)(addr)) : "memory")

#define MBARRIER_WAIT_PARITY(addr, parity) do {                                    \
    uint32_t _m = (uint32_t)(addr), _p = (uint32_t)(parity), _d;                   \
    asm volatile("{\n\t.reg .pred p;\n\t"                                          \
        "mbarrier.try_wait.parity.acquire.cta.shared::cta.b64 p, [%1], %2;\n\t"    \
        "selp.b32 %0, 1, 0, p;\n\t}" : "=r"(_d) : "r"(_m), "r"(_p) : "memory");    \
    if (!_d) {                                                                     \
        asm volatile("{\n\t.reg .pred P1;\n\t"                                     \
            "WL_%=:\n\t"                                                           \
            "mbarrier.try_wait.parity.acquire.cta.shared::cta.b64 P1, [%0], %1, 0x989680;\n\t" \
            "@P1 bra.uni WD_%=;\n\tbra.uni WL_%=;\n\tWD_%=:\n\t}"                  \
            :: "r"(_m), "r"(_p) : "memory");                                       \
    }                                                                              \
} while (0)

#define FENCE_PROXY_ASYNC()    asm volatile("fence.proxy.async.shared::cta;" ::: "memory")

// SW128 descriptor: layout=2, version=1, SBO=64, LBO=1
static constexpr uint64_t DESC_BASE_SW128 =
    (uint64_t(2) << 61) | (uint64_t(1) << 46) | (uint64_t(64) << 32) | (uint64_t(1) << 16);
#define MAKE_DESC(addr) (DESC_BASE_SW128 | ((uint64_t)((addr) >> 4) & 0x3FFF))

__device__ __forceinline__ uint32_t sw128(uint32_t o) { return o ^ ((o >> 3) & 0x70); }

// idesc: fp32 accum, bf16 A/B, M=128, N=128
static constexpr uint32_t IDESC =
    (1u << 4) | (1u << 7) | (1u << 10) | ((128u / 8) << 17) | ((128u / 16) << 24);

// ---------------- smem layout ------------------------------------------------
#define SM_TMEM   0
#define SM_FULL   16
#define SM_EMPTY  40
#define SM_DONE   64
#define SM_TILES  1024
#define STAGE_SZ  65536
#define NSTAGE    3
#define SMEM_TOTAL (SM_TILES + NSTAGE * STAGE_SZ)
#define NCTA      128

// ---------------- persistent fused kernel ------------------------------------
// grid (64, 2) = 128 CTAs (one per SM, all resident -> grid barrier is safe).
// 544 threads: warps 0-15 producers, warp 16 lane 0 = MMA issuer.
__global__ __launch_bounds__(544, 1)
void cheb_persist(const float* __restrict__ L,
                  const float* __restrict__ x,
                  const float* __restrict__ W,
                  float* __restrict__ out)
{
#if HAS_TCGEN05
    extern __shared__ char smem[];
    const uint32_t sbase = smem_u32(smem);
    const int tid = threadIdx.x;
    const int wid = tid >> 5, lid = tid & 31;
    const int mBase = blockIdx.x * 128;
    const int khalf = blockIdx.y;
    const int kStart = khalf * 4096;
    const int cta = blockIdx.x + blockIdx.y * 64;   // 0..127

    if (wid == 0)
        asm volatile("tcgen05.alloc.cta_group::1.sync.aligned.shared::cta.b32 [%0], %1;"
                     :: "r"(sbase + SM_TMEM), "r"(128u) : "memory");
    if (tid == 0) {
#pragma unroll
        for (int s = 0; s < NSTAGE; s++) {
            MBARRIER_INIT(sbase + SM_FULL + 8 * s, 16);
            MBARRIER_INIT(sbase + SM_EMPTY + 8 * s, 1);
        }
        MBARRIER_INIT(sbase + SM_DONE, 1);
    }
    __syncthreads();
    uint32_t tmem;
    asm volatile("ld.shared.b32 %0, [%1];" : "=r"(tmem) : "r"(sbase + SM_TMEM));

    int phE[NSTAGE] = {0, 0, 0};
    int phF[NSTAGE] = {0, 0, 0};

    // per-thread B addressing (producers)
    const int p = tid;
    const int bRow0 = p >> 3, bG0 = p & 7;
    const int bRow1 = (p + 512) >> 3, bG1 = (p + 512) & 7;
    const uint32_t bOff0 = sw128((uint32_t)(bRow0 * 128 + bG0 * 16));
    const uint32_t bOff1 = sw128((uint32_t)(bRow1 * 128 + bG1 * 16));

    for (int kpass = 0; kpass < 2; kpass++) {
        // ============ GEMM pass: P[khalf] = L[tile] @ Bt^T ==================
        if (wid < 16) {
            // ---- producers ------------------------------------------------
            // prologue: A(0) regs (streaming) + B(0) into ring slot
            float4 va[4];
#pragma unroll
            for (int i = 0; i < 4; i++) {
                int f = p + i * 512;
                int row = f >> 4, cg = f & 15;
                va[i] = __ldcs((const float4*)(L + (size_t)(mBase + row) * NN + kStart + cg * 4));
            }
            {
                const int nIss = kpass * 64;            // global B-issue index
                const int s0 = nIss % 3;
                if (nIss >= 3) { MBARRIER_WAIT_PARITY(sbase + SM_EMPTY + 8 * s0, phE[s0]); phE[s0] ^= 1; }
                const uint32_t stg0 = sbase + SM_TILES + s0 * STAGE_SZ;
                size_t sa = (size_t)bRow0 * NN + kStart + bG0 * 8;
                size_t sb = (size_t)bRow1 * NN + kStart + bG1 * 8;
                asm volatile("cp.async.cg.shared.global [%0], [%1], 16;" :: "r"(stg0 + 32768 + bOff0), "l"(g_Bt_hi + sa) : "memory");
                asm volatile("cp.async.cg.shared.global [%0], [%1], 16;" :: "r"(stg0 + 49152 + bOff0), "l"(g_Bt_lo + sa) : "memory");
                asm volatile("cp.async.cg.shared.global [%0], [%1], 16;" :: "r"(stg0 + 32768 + bOff1), "l"(g_Bt_hi + sb) : "memory");
                asm volatile("cp.async.cg.shared.global [%0], [%1], 16;" :: "r"(stg0 + 49152 + bOff1), "l"(g_Bt_lo + sb) : "memory");
                asm volatile("cp.async.commit_group;" ::: "memory");
            }

            for (int c = 0; c < 64; c++) {
                const int sA = (kpass * 64 + c) % 3;
                char* stgp = smem + SM_TILES + sA * STAGE_SZ;

                // A(c+1) prefetch (streaming; keep B L2-resident)
                float4 vb[4];
                if (c + 1 < 64) {
                    const int kNext = kStart + (c + 1) * 64;
#pragma unroll
                    for (int i = 0; i < 4; i++) {
                        int f = p + i * 512;
                        int row = f >> 4, cg = f & 15;
                        vb[i] = __ldcs((const float4*)(L + (size_t)(mBase + row) * NN + kNext + cg * 4));
                    }
                }

                // convert + store A(c) — rounded bf16 split
#pragma unroll
                for (int i = 0; i < 4; i++) {
                    int f = p + i * 512;
                    int row = f >> 4, cg = f & 15;
                    float4 v = va[i];
                    __nv_bfloat16 h0 = __float2bfloat16(v.x), h1 = __float2bfloat16(v.y);
                    __nv_bfloat16 h2 = __float2bfloat16(v.z), h3 = __float2bfloat16(v.w);
                    __nv_bfloat16 l0 = __float2bfloat16(v.x - __bfloat162float(h0));
                    __nv_bfloat16 l1 = __float2bfloat16(v.y - __bfloat162float(h1));
                    __nv_bfloat16 l2 = __float2bfloat16(v.z - __bfloat162float(h2));
                    __nv_bfloat16 l3 = __float2bfloat16(v.w - __bfloat162float(h3));
                    uint2 hp, lp;
                    hp.x = (uint32_t)__bfloat16_as_ushort(h0) | ((uint32_t)__bfloat16_as_ushort(h1) << 16);
                    hp.y = (uint32_t)__bfloat16_as_ushort(h2) | ((uint32_t)__bfloat16_as_ushort(h3) << 16);
                    lp.x = (uint32_t)__bfloat16_as_ushort(l0) | ((uint32_t)__bfloat16_as_ushort(l1) << 16);
                    lp.y = (uint32_t)__bfloat16_as_ushort(l2) | ((uint32_t)__bfloat16_as_ushort(l3) << 16);
                    uint32_t off = sw128((uint32_t)(row * 128 + cg * 8));
                    *(uint2*)(stgp + off) = hp;
                    *(uint2*)(stgp + 16384 + off) = lp;
                }

                // B(c+1) one stage ahead (empty-wait as late as possible)
                if (c + 1 < 64) {
                    const int nIss = kpass * 64 + c + 1;
                    const int sn = nIss % 3;
                    if (nIss >= 3) { MBARRIER_WAIT_PARITY(sbase + SM_EMPTY + 8 * sn, phE[sn]); phE[sn] ^= 1; }
                    const uint32_t stgN = sbase + SM_TILES + sn * STAGE_SZ;
                    const int kNext = kStart + (c + 1) * 64;
                    size_t sa = (size_t)bRow0 * NN + kNext + bG0 * 8;
                    size_t sb = (size_t)bRow1 * NN + kNext + bG1 * 8;
                    asm volatile("cp.async.cg.shared.global [%0], [%1], 16;" :: "r"(stgN + 32768 + bOff0), "l"(g_Bt_hi + sa) : "memory");
                    asm volatile("cp.async.cg.shared.global [%0], [%1], 16;" :: "r"(stgN + 49152 + bOff0), "l"(g_Bt_lo + sa) : "memory");
                    asm volatile("cp.async.cg.shared.global [%0], [%1], 16;" :: "r"(stgN + 32768 + bOff1), "l"(g_Bt_hi + sb) : "memory");
                    asm volatile("cp.async.cg.shared.global [%0], [%1], 16;" :: "r"(stgN + 49152 + bOff1), "l"(g_Bt_lo + sb) : "memory");
                    asm volatile("cp.async.commit_group;" ::: "memory");
                    asm volatile("cp.async.wait_group 1;" ::: "memory");   // B(c) done
                } else {
                    asm volatile("cp.async.wait_group 0;" ::: "memory");
                }
                __syncwarp();
                if (lid == 0) MBARRIER_ARRIVE(sbase + SM_FULL + 8 * sA);
                va[0] = vb[0]; va[1] = vb[1]; va[2] = vb[2]; va[3] = vb[3];
            }
        } else if (lid == 0) {
            // ---- MMA issuer ------------------------------------------------
            for (int c = 0; c < 64; c++) {
                const int sI = (kpass * 64 + c) % 3;
                MBARRIER_WAIT_PARITY(sbase + SM_FULL + 8 * sI, phF[sI]);
                phF[sI] ^= 1;
                FENCE_PROXY_ASYNC();
                const uint32_t stg = sbase + SM_TILES + sI * STAGE_SZ;
                uint64_t dAh = MAKE_DESC(stg);
                uint64_t dAl = MAKE_DESC(stg + 16384);
                uint64_t dBh = MAKE_DESC(stg + 32768);
                uint64_t dBl = MAKE_DESC(stg + 49152);
#pragma unroll
                for (int ks = 0; ks < 4; ks++) {
                    uint32_t en = (c > 0 || ks > 0) ? 1u : 0u;
                    asm volatile(
                        "{\n\t.reg .pred p;\n\tsetp.ne.u32 p, %5, 0;\n\t"
                        "tcgen05.mma.cta_group::1.kind::f16 [%0], %1, %2, %3, {%4,%4,%4,%4}, p;\n\t}"
                        :: "r"(tmem), "l"(dAh + ks * 2), "l"(dBh + ks * 2), "r"(IDESC), "r"(0u), "r"(en) : "memory");
                }
#pragma unroll
                for (int ks = 0; ks < 4; ks++)
                    asm volatile(
                        "{\n\t.reg .pred p;\n\tsetp.ne.u32 p, %5, 0;\n\t"
                        "tcgen05.mma.cta_group::1.kind::f16 [%0], %1, %2, %3, {%4,%4,%4,%4}, p;\n\t}"
                        :: "r"(tmem), "l"(dAh + ks * 2), "l"(dBl + ks * 2), "r"(IDESC), "r"(0u), "r"(1u) : "memory");
#pragma unroll
                for (int ks = 0; ks < 4; ks++)
                    asm volatile(
                        "{\n\t.reg .pred p;\n\tsetp.ne.u32 p, %5, 0;\n\t"
                        "tcgen05.mma.cta_group::1.kind::f16 [%0], %1, %2, %3, {%4,%4,%4,%4}, p;\n\t}"
                        :: "r"(tmem), "l"(dAl + ks * 2), "l"(dBh + ks * 2), "r"(IDESC), "r"(0u), "r"(1u) : "memory");
                asm volatile("tcgen05.commit.cta_group::1.mbarrier::arrive::one.shared::cluster.b64 [%0];"
                             :: "r"(sbase + SM_EMPTY + 8 * sI) : "memory");
            }
            asm volatile("tcgen05.commit.cta_group::1.mbarrier::arrive::one.shared::cluster.b64 [%0];"
                         :: "r"(sbase + SM_DONE) : "memory");
        }

        // ---- wait for all MMAs of this pass; epilogue to P -----------------
        MBARRIER_WAIT_PARITY(sbase + SM_DONE, kpass);
        asm volatile("tcgen05.fence::after_thread_sync;" ::: "memory");
        if (wid < 4) {
            const int m = mBase + wid * 32 + lid;
            float* dst = g_P + (size_t)khalf * NN * CC + (size_t)m * CC;
#pragma unroll
            for (int cb = 0; cb < 128; cb += 32) {
                uint32_t r[32];
                asm volatile("tcgen05.ld.sync.aligned.32x32b.x32.b32 "
                    "{%0,%1,%2,%3,%4,%5,%6,%7,%8,%9,%10,%11,%12,%13,%14,%15,"
                    "%16,%17,%18,%19,%20,%21,%22,%23,%24,%25,%26,%27,%28,%29,%30,%31}, [%32];"
                    : "=r"(r[0]),"=r"(r[1]),"=r"(r[2]),"=r"(r[3]),"=r"(r[4]),"=r"(r[5]),"=r"(r[6]),"=r"(r[7]),
                      "=r"(r[8]),"=r"(r[9]),"=r"(r[10]),"=r"(r[11]),"=r"(r[12]),"=r"(r[13]),"=r"(r[14]),"=r"(r[15]),
                      "=r"(r[16]),"=r"(r[17]),"=r"(r[18]),"=r"(r[19]),"=r"(r[20]),"=r"(r[21]),"=r"(r[22]),"=r"(r[23]),
                      "=r"(r[24]),"=r"(r[25]),"=r"(r[26]),"=r"(r[27]),"=r"(r[28]),"=r"(r[29]),"=r"(r[30]),"=r"(r[31])
                    : "r"(tmem + cb));
                asm volatile("tcgen05.wait::ld.sync.aligned;" ::: "memory");
#pragma unroll
                for (int j = 0; j < 32; j += 4) {
                    float4 v = { __uint_as_float(r[j]), __uint_as_float(r[j + 1]),
                                 __uint_as_float(r[j + 2]), __uint_as_float(r[j + 3]) };
                    *(float4*)(dst + cb + j) = v;
                }
            }
            asm volatile("tcgen05.fence::before_thread_sync;" ::: "memory");
        }

        // ---- grid barrier ---------------------------------------------------
        {
            unsigned* cnt = (kpass == 0) ? &g_cnt1 : &g_cnt3;
            __syncthreads();
            if (tid == 0) {
                __threadfence();
                atomicAdd(cnt, 1u);
                while (atomicAdd(cnt, 0u) < NCTA) __nanosleep(64);
                __threadfence();
            }
            __syncthreads();
        }

        // ---- between passes: T1 = P0+P1 + transposed split ------------------
        if (kpass == 0) {
            float* tile = (float*)(smem + SM_TILES);        // [32][33]
            for (int i = 0; i < 8; i++) {
                int t = cta * 8 + i;                        // 0..1023
                int n0 = (t & 255) * 32, c0 = (t >> 8) * 32;
                if (tid < 256) {
                    int tx = tid & 31, ty = tid >> 5;       // ty 0..7
#pragma unroll
                    for (int r = 0; r < 4; r++) {
                        int row = ty + 8 * r;
                        size_t o = (size_t)(n0 + row) * CC + c0 + tx;
                        float v = g_P[o] + g_P[(size_t)NN * CC + o];
                        g_T1[o] = v;
                        tile[row * 33 + tx] = v;
                    }
                }
                __syncthreads();
                if (tid < 256) {
                    int tx = tid & 31, ty = tid >> 5;
#pragma unroll
                    for (int r = 0; r < 4; r++) {
                        int crow = ty + 8 * r;
                        float v = tile[tx * 33 + crow];
                        __nv_bfloat16 h = __float2bfloat16(v);
                        size_t o = (size_t)(c0 + crow) * NN + n0 + tx;
                        g_Bt_hi[o] = h;
                        g_Bt_lo[o] = __float2bfloat16(v - __bfloat162float(h));
                    }
                }
                __syncthreads();
            }
            // barrier 2: Bt fully written before pass 2 reads it
            __syncthreads();
            if (tid == 0) {
                __threadfence();
                atomicAdd(&g_cnt2, 1u);
                while (atomicAdd(&g_cnt2, 0u) < NCTA) __nanosleep(64);
                __threadfence();
            }
            __syncthreads();
        }
    }

    // ================= output: out = x@W0^T + T1@W1^T + T2@W2^T =============
    {
        float* T2s = (float*)(smem + SM_TILES);             // [64][132] padded
        float* As  = (float*)(smem + SM_TILES + 34816);     // [16][64]
        float* Ws  = (float*)(smem + SM_TILES + 34816 + 4096); // [16][128]
        const int rowBase = cta * 64;
        const int tx = tid & 31, ty = tid >> 5;

        if (tid < 256) {
#pragma unroll
            for (int i = 0; i < 8; i++) {
                int f = tid + i * 256;
                int r = f >> 5, cg = f & 31;
                size_t o = (size_t)(rowBase + r) * CC + cg * 4;
                float4 p0 = *(const float4*)(g_P + o);
                float4 p1 = *(const float4*)(g_P + (size_t)NN * CC + o);
                float4 xv = *(const float4*)(x + o);
                T2s[r * 132 + cg * 4 + 0] = 2.0f * (p0.x + p1.x) - xv.x;
                T2s[r * 132 + cg * 4 + 1] = 2.0f * (p0.y + p1.y) - xv.y;
                T2s[r * 132 + cg * 4 + 2] = 2.0f * (p0.z + p1.z) - xv.z;
                T2s[r * 132 + cg * 4 + 3] = 2.0f * (p0.w + p1.w) - xv.w;
            }
        }
        __syncthreads();

        float acc[8][4];
#pragma unroll
        for (int i = 0; i < 8; i++)
#pragma unroll
            for (int j = 0; j < 4; j++) acc[i][j] = 0.0f;

        const float* Amats[2] = {x, g_T1};
        for (int jm = 0; jm < 3; jm++) {
            const float* Wj = W + (size_t)jm * CC * CC;
            for (int k0 = 0; k0 < CC; k0 += 16) {
                if (tid < 256) {
                    int r = tid >> 2, cg = tid & 3;
                    float4 v;
                    if (jm < 2)
                        v = *(const float4*)(Amats[jm] + (size_t)(rowBase + r) * CC + k0 + cg * 4);
                    else {
                        v.x = T2s[r * 132 + k0 + cg * 4 + 0];
                        v.y = T2s[r * 132 + k0 + cg * 4 + 1];
                        v.z = T2s[r * 132 + k0 + cg * 4 + 2];
                        v.w = T2s[r * 132 + k0 + cg * 4 + 3];
                    }
                    As[(cg * 4 + 0) * 64 + r] = v.x; As[(cg * 4 + 1) * 64 + r] = v.y;
                    As[(cg * 4 + 2) * 64 + r] = v.z; As[(cg * 4 + 3) * 64 + r] = v.w;
#pragma unroll
                    for (int i = 0; i < 2; i++) {
                        int f = tid * 2 + i;
                        int n = f >> 2, cg2 = f & 3;
                        float4 w = *(const float4*)(Wj + (size_t)n * CC + k0 + cg2 * 4);
                        Ws[(cg2 * 4 + 0) * 128 + n] = w.x; Ws[(cg2 * 4 + 1) * 128 + n] = w.y;
                        Ws[(cg2 * 4 + 2) * 128 + n] = w.z; Ws[(cg2 * 4 + 3) * 128 + n] = w.w;
                    }
                }
                __syncthreads();
                if (tid < 256) {
#pragma unroll
                    for (int kk = 0; kk < 16; kk++) {
                        float4 a0 = *(const float4*)(&As[kk * 64 + ty * 8 + 0]);
                        float4 a1 = *(const float4*)(&As[kk * 64 + ty * 8 + 4]);
                        float4 b0 = *(const float4*)(&Ws[kk * 128 + tx * 4]);
                        float a[8] = {a0.x, a0.y, a0.z, a0.w, a1.x, a1.y, a1.z, a1.w};
                        float b[4] = {b0.x, b0.y, b0.z, b0.w};
#pragma unroll
                        for (int i = 0; i < 8; i++)
#pragma unroll
                            for (int j = 0; j < 4; j++) acc[i][j] += a[i] * b[j];
                    }
                }
                __syncthreads();
            }
        }
        if (tid < 256) {
#pragma unroll
            for (int i = 0; i < 8; i++) {
                size_t off = (size_t)(rowBase + ty * 8 + i) * CC + tx * 4;
                float4 v = {acc[i][0], acc[i][1], acc[i][2], acc[i][3]};
                *(float4*)(out + off) = v;
            }
        }
    }

    __syncthreads();
    if (wid == 0) {
        asm volatile("tcgen05.relinquish_alloc_permit.cta_group::1.sync.aligned;");
        asm volatile("tcgen05.dealloc.cta_group::1.sync.aligned.b32 %0, %1;" :: "r"(tmem), "r"(128u));
    }
#else
    // Fallback body for the non-'a' PTX pass (never executed on GB300).
    (void)L; (void)x; (void)W; (void)out;
#endif
}

// ---------------- transpose-split: Bt = split(x^T) + counter reset -----------
// grid (NN/32, CC/32), block (32, 8)
__global__ void convert_x(const float* __restrict__ x)
{
    __shared__ float tile[32][33];
    if (blockIdx.x == 0 && blockIdx.y == 0 && threadIdx.x == 0 && threadIdx.y == 0) {
        g_cnt1 = 0; g_cnt2 = 0; g_cnt3 = 0;   // reset grid-barrier counters
    }
    const int n0 = blockIdx.x * 32, c0 = blockIdx.y * 32;
    const int tx = threadIdx.x, ty = threadIdx.y;
#pragma unroll
    for (int r = 0; r < 4; r++) {
        int row = ty + 8 * r;
        tile[row][tx] = x[(size_t)(n0 + row) * CC + c0 + tx];
    }
    __syncthreads();
#pragma unroll
    for (int r = 0; r < 4; r++) {
        int crow = ty + 8 * r;
        float v = tile[tx][crow];                    // = x[n0+tx][c0+crow]
        __nv_bfloat16 h = __float2bfloat16(v);
        size_t o = (size_t)(c0 + crow) * NN + n0 + tx;
        g_Bt_hi[o] = h;
        g_Bt_lo[o] = __float2bfloat16(v - __bfloat162float(h));
    }
}

// ---------------- launch -----------------------------------------------------
extern "C" void kernel_launch(void* const* d_in, const int* in_sizes, int n_in,
                              void* d_out, int out_size)
{
    const float *x = nullptr, *L = nullptr, *W = nullptr;
    for (int i = 0; i < n_in; i++) {
        long long sz = in_sizes[i];
        if (sz == (long long)NN * NN)      L = (const float*)d_in[i];
        else if (sz == 3LL * CC * CC)      W = (const float*)d_in[i];
        else if (sz == (long long)NN * CC) x = (const float*)d_in[i];
    }
    float* out = (float*)d_out;

    cudaFuncSetAttribute(cheb_persist, cudaFuncAttributeMaxDynamicSharedMemorySize, SMEM_TOTAL);

    dim3 gTr(NN / 32, CC / 32);
    dim3 bTr(32, 8);
    convert_x<<<gTr, bTr>>>(x);                    // also resets barrier counters
    cheb_persist<<<dim3(64, 2), 544, SMEM_TOTAL>>>(L, x, W, out);
}